// round 2
// baseline (speedup 1.0000x reference)
#include <cuda_runtime.h>
#include <math.h>
#include <stdint.h>

// Problem constants
#define BB 1024   // batch (edges per direction)
#define NN 1024   // nodes
#define DD 256    // feature dim
#define K3 768    // 3*D

// ---------------- static scratch (no allocations allowed) ----------------
__device__ float g_X[2 * BB * K3];    // gathered MLP inputs: rows [0,1024)=src, [1024,2048)=tgt  (6 MB)
__device__ float g_H[2 * BB * DD];    // hidden after relu (2 MB)
__device__ float g_MSG[2 * BB * DD];  // messages (2 MB)
__device__ float g_AGG[NN * DD];      // segment mean (1 MB)
__device__ int   g_CNT[NN];           // per-node edge counts
__device__ float g_G[2 * NN * K3];    // rows [0,1024)=gi, [1024,2048)=gh (6 MB)

// ---------------- gather: build concat inputs for both MLPs ----------------
__global__ void gather_kernel(const float* __restrict__ memory,
                              const int* __restrict__ src,
                              const int* __restrict__ tgt,
                              const float* __restrict__ dtv) {
    int b = blockIdx.x;
    int d = threadIdx.x;
    int s = src[b];
    int t = tgt[b];
    float ms = memory[(size_t)s * DD + d];
    float mt = memory[(size_t)t * DD + d];
    float ds = dtv[((size_t)b * NN + s) * DD + d];
    float dt = dtv[((size_t)b * NN + t) * DD + d];
    float* xs = g_X + (size_t)b * K3;
    float* xt = g_X + (size_t)(BB + b) * K3;
    xs[d]          = ms;  // [src_mem, tgt_mem, src_dt]
    xs[DD + d]     = mt;
    xs[2 * DD + d] = ds;
    xt[d]          = mt;  // [tgt_mem, src_mem, tgt_dt]
    xt[DD + d]     = ms;
    xt[2 * DD + d] = dt;
}

// ---------------- generic dual-half GEMM:  C[m,n] = act( A[m,:] . W[n,:] + bias[n] )
// rows [0,halfM) use (A0,W0,b0); rows [halfM,2*halfM) use (A1,W1,b1) with local row index.
// BM=BN=64, BK=16, 256 threads, 4x4 register tile per thread.
__global__ __launch_bounds__(256) void gemm_kernel(
    const float* __restrict__ A0, const float* __restrict__ A1,
    const float* __restrict__ W0, const float* __restrict__ W1,
    const float* __restrict__ b0, const float* __restrict__ b1,
    float* __restrict__ C, int halfM, int Nn, int Kk, int doRelu) {

    __shared__ __align__(16) float As[16][68];
    __shared__ __align__(16) float Bs[16][68];

    const int tid  = threadIdx.x;
    const int row0 = blockIdx.y * 64;
    const int col0 = blockIdx.x * 64;

    const bool hi = (row0 >= halfM);
    const float* __restrict__ Aptr = hi ? A1 : A0;
    const float* __restrict__ Wptr = hi ? W1 : W0;
    const float* __restrict__ bptr = hi ? b1 : b0;
    const int arow0 = row0 - (hi ? halfM : 0);

    const int ldr = tid >> 2;        // 0..63 (row of A tile / col of W tile)
    const int ldk = (tid & 3) * 4;   // 0,4,8,12

    const int tm = tid >> 4;         // 0..15
    const int tn = tid & 15;         // 0..15

    float acc[4][4];
#pragma unroll
    for (int i = 0; i < 4; i++)
#pragma unroll
        for (int j = 0; j < 4; j++) acc[i][j] = 0.0f;

    for (int kt = 0; kt < Kk; kt += 16) {
        float4 av = *reinterpret_cast<const float4*>(
            &Aptr[(size_t)(arow0 + ldr) * Kk + kt + ldk]);
        float4 wv = *reinterpret_cast<const float4*>(
            &Wptr[(size_t)(col0 + ldr) * Kk + kt + ldk]);
        As[ldk + 0][ldr] = av.x;
        As[ldk + 1][ldr] = av.y;
        As[ldk + 2][ldr] = av.z;
        As[ldk + 3][ldr] = av.w;
        Bs[ldk + 0][ldr] = wv.x;
        Bs[ldk + 1][ldr] = wv.y;
        Bs[ldk + 2][ldr] = wv.z;
        Bs[ldk + 3][ldr] = wv.w;
        __syncthreads();

#pragma unroll
        for (int k = 0; k < 16; k++) {
            float4 a = *reinterpret_cast<const float4*>(&As[k][tm * 4]);
            float4 b = *reinterpret_cast<const float4*>(&Bs[k][tn * 4]);
            acc[0][0] += a.x * b.x; acc[0][1] += a.x * b.y; acc[0][2] += a.x * b.z; acc[0][3] += a.x * b.w;
            acc[1][0] += a.y * b.x; acc[1][1] += a.y * b.y; acc[1][2] += a.y * b.z; acc[1][3] += a.y * b.w;
            acc[2][0] += a.z * b.x; acc[2][1] += a.z * b.y; acc[2][2] += a.z * b.z; acc[2][3] += a.z * b.w;
            acc[3][0] += a.w * b.x; acc[3][1] += a.w * b.y; acc[3][2] += a.w * b.z; acc[3][3] += a.w * b.w;
        }
        __syncthreads();
    }

    const int gcol = col0 + tn * 4;
    float4 bias4 = *reinterpret_cast<const float4*>(&bptr[gcol]);
#pragma unroll
    for (int i = 0; i < 4; i++) {
        int grow = row0 + tm * 4 + i;
        float4 v;
        v.x = acc[i][0] + bias4.x;
        v.y = acc[i][1] + bias4.y;
        v.z = acc[i][2] + bias4.z;
        v.w = acc[i][3] + bias4.w;
        if (doRelu) {
            v.x = fmaxf(v.x, 0.0f);
            v.y = fmaxf(v.y, 0.0f);
            v.z = fmaxf(v.z, 0.0f);
            v.w = fmaxf(v.w, 0.0f);
        }
        *reinterpret_cast<float4*>(&C[(size_t)grow * Nn + gcol]) = v;
    }
}

// ---------------- deterministic segment mean ----------------
// One block per node. Warp 0 builds an ordered list of matching edges
// (ballot + popc prefix -> deterministic ascending edge order), then all
// 256 threads (one per feature d) reduce in list order.
__global__ void segment_kernel(const int* __restrict__ src,
                               const int* __restrict__ tgt) {
    __shared__ int s_list[2 * BB];
    __shared__ int s_cnt;
    const int n = blockIdx.x;
    const int tid = threadIdx.x;

    if (tid < 32) {
        int base = 0;
        for (int e0 = 0; e0 < 2 * BB; e0 += 32) {
            int e = e0 + tid;
            int node = (e < BB) ? src[e] : tgt[e - BB];
            unsigned m = __ballot_sync(0xffffffffu, node == n);
            if (node == n) {
                int pos = base + __popc(m & ((1u << tid) - 1u));
                s_list[pos] = e;
            }
            base += __popc(m);
        }
        if (tid == 0) s_cnt = base;
    }
    __syncthreads();

    const int cnt = s_cnt;
    float sum = 0.0f;
    for (int i = 0; i < cnt; i++) {
        int e = s_list[i];
        sum += g_MSG[(size_t)e * DD + tid];
    }
    float denom = (cnt > 0) ? (float)cnt : 1.0f;
    g_AGG[(size_t)n * DD + tid] = sum / denom;
    if (tid == 0) g_CNT[n] = cnt;
}

// ---------------- GRU gates + masked write ----------------
__global__ void gate_kernel(const float* __restrict__ memory,
                            float* __restrict__ out) {
    const int n = blockIdx.x;
    const int d = threadIdx.x;
    const float* gi = g_G + (size_t)n * K3;
    const float* gh = g_G + (size_t)(NN + n) * K3;

    float r  = 1.0f / (1.0f + expf(-(gi[d] + gh[d])));
    float z  = 1.0f / (1.0f + expf(-(gi[DD + d] + gh[DD + d])));
    float nn = tanhf(gi[2 * DD + d] + r * gh[2 * DD + d]);
    float h  = memory[(size_t)n * DD + d];
    float nv = (1.0f - z) * nn + z * h;
    out[(size_t)n * DD + d] = (g_CNT[n] > 0) ? nv : h;
}

// ---------------- launch ----------------
extern "C" void kernel_launch(void* const* d_in, const int* in_sizes, int n_in,
                              void* d_out, int out_size) {
    const float* memory  = (const float*)d_in[0];
    const int*   source  = (const int*)d_in[1];
    const int*   target  = (const int*)d_in[2];
    const float* dtv     = (const float*)d_in[3];
    const float* src_w1  = (const float*)d_in[4];
    const float* src_b1  = (const float*)d_in[5];
    const float* src_w2  = (const float*)d_in[6];
    const float* src_b2  = (const float*)d_in[7];
    const float* tar_w1  = (const float*)d_in[8];
    const float* tar_b1  = (const float*)d_in[9];
    const float* tar_w2  = (const float*)d_in[10];
    const float* tar_b2  = (const float*)d_in[11];
    const float* gru_wih = (const float*)d_in[12];
    const float* gru_whh = (const float*)d_in[13];
    const float* gru_bih = (const float*)d_in[14];
    const float* gru_bhh = (const float*)d_in[15];
    float* out = (float*)d_out;

    float *pX, *pH, *pMSG, *pAGG, *pG;
    cudaGetSymbolAddress((void**)&pX,   g_X);
    cudaGetSymbolAddress((void**)&pH,   g_H);
    cudaGetSymbolAddress((void**)&pMSG, g_MSG);
    cudaGetSymbolAddress((void**)&pAGG, g_AGG);
    cudaGetSymbolAddress((void**)&pG,   g_G);

    // 1) gather concat inputs
    gather_kernel<<<BB, DD>>>(memory, source, target, dtv);

    // 2) MLP layer 1 (relu): X[2048,768] -> H[2048,256]
    gemm_kernel<<<dim3(DD / 64, (2 * BB) / 64), 256>>>(
        pX, pX + (size_t)BB * K3, src_w1, tar_w1, src_b1, tar_b1,
        pH, BB, DD, K3, 1);

    // 3) MLP layer 2: H[2048,256] -> MSG[2048,256]
    gemm_kernel<<<dim3(DD / 64, (2 * BB) / 64), 256>>>(
        pH, pH + (size_t)BB * DD, src_w2, tar_w2, src_b2, tar_b2,
        pMSG, BB, DD, DD, 0);

    // 4) deterministic segment mean -> AGG[1024,256], CNT
    segment_kernel<<<NN, DD>>>(source, target);

    // 5) GRU preactivations: gi = agg@wih^T + bih ; gh = memory@whh^T + bhh
    gemm_kernel<<<dim3(K3 / 64, (2 * NN) / 64), 256>>>(
        pAGG, memory, gru_wih, gru_whh, gru_bih, gru_bhh,
        pG, NN, K3, DD, 0);

    // 6) gates + masked output
    gate_kernel<<<NN, DD>>>(memory, out);
}

// round 5
// speedup vs baseline: 1.0987x; 1.0987x over previous
#include <cuda_runtime.h>
#include <math.h>
#include <stdint.h>

// Problem constants
#define BB 1024   // batch (edges per direction)
#define NN 1024   // nodes
#define DD 256    // feature dim
#define K3 768    // 3*D

// ---------------- static scratch (no allocations allowed) ----------------
__device__ float g_X[2 * BB * K3];    // gathered MLP inputs: rows [0,1024)=src, [1024,2048)=tgt  (6 MB)
__device__ float g_H[2 * BB * DD];    // hidden after relu (2 MB)
__device__ float g_MSG[2 * BB * DD];  // messages (2 MB)
__device__ float g_AGG[NN * DD];      // segment mean (1 MB)
__device__ int   g_CNT[NN];           // per-node edge counts
__device__ float g_G[2 * NN * K3];    // rows [0,1024)=gi, [1024,2048)=gh (6 MB)

// ---------------- gather: build concat inputs for both MLPs ----------------
__global__ void gather_kernel(const float* __restrict__ memory,
                              const int* __restrict__ src,
                              const int* __restrict__ tgt,
                              const float* __restrict__ dtv) {
    int b = blockIdx.x;
    int d = threadIdx.x;
    int s = src[b];
    int t = tgt[b];
    float ms = memory[(size_t)s * DD + d];
    float mt = memory[(size_t)t * DD + d];
    float ds = dtv[((size_t)b * NN + s) * DD + d];
    float dt = dtv[((size_t)b * NN + t) * DD + d];
    float* xs = g_X + (size_t)b * K3;
    float* xt = g_X + (size_t)(BB + b) * K3;
    xs[d]          = ms;  // [src_mem, tgt_mem, src_dt]
    xs[DD + d]     = mt;
    xs[2 * DD + d] = ds;
    xt[d]          = mt;  // [tgt_mem, src_mem, tgt_dt]
    xt[DD + d]     = ms;
    xt[2 * DD + d] = dt;
}

// ---------------- generic dual-half GEMM:  C[m,n] = act( A[m,:] . W[n,:] + bias[n] )
// rows [0,halfM) use (A0,W0,b0); rows [halfM,2*halfM) use (A1,W1,b1) with local row index.
// BM=BN=64, BK=16, 256 threads, 4x4 register tile per thread.
__global__ __launch_bounds__(256) void gemm_kernel(
    const float* __restrict__ A0, const float* __restrict__ A1,
    const float* __restrict__ W0, const float* __restrict__ W1,
    const float* __restrict__ b0, const float* __restrict__ b1,
    float* __restrict__ C, int halfM, int Nn, int Kk, int doRelu) {

    __shared__ __align__(16) float As[16][68];
    __shared__ __align__(16) float Bs[16][68];

    const int tid  = threadIdx.x;
    const int row0 = blockIdx.y * 64;
    const int col0 = blockIdx.x * 64;

    const bool hi = (row0 >= halfM);
    const float* __restrict__ Aptr = hi ? A1 : A0;
    const float* __restrict__ Wptr = hi ? W1 : W0;
    const float* __restrict__ bptr = hi ? b1 : b0;
    const int arow0 = row0 - (hi ? halfM : 0);

    const int ldr = tid >> 2;        // 0..63 (row of A tile / col of W tile)
    const int ldk = (tid & 3) * 4;   // 0,4,8,12

    const int tm = tid >> 4;         // 0..15
    const int tn = tid & 15;         // 0..15

    float acc[4][4];
#pragma unroll
    for (int i = 0; i < 4; i++)
#pragma unroll
        for (int j = 0; j < 4; j++) acc[i][j] = 0.0f;

    for (int kt = 0; kt < Kk; kt += 16) {
        float4 av = *reinterpret_cast<const float4*>(
            &Aptr[(size_t)(arow0 + ldr) * Kk + kt + ldk]);
        float4 wv = *reinterpret_cast<const float4*>(
            &Wptr[(size_t)(col0 + ldr) * Kk + kt + ldk]);
        As[ldk + 0][ldr] = av.x;
        As[ldk + 1][ldr] = av.y;
        As[ldk + 2][ldr] = av.z;
        As[ldk + 3][ldr] = av.w;
        Bs[ldk + 0][ldr] = wv.x;
        Bs[ldk + 1][ldr] = wv.y;
        Bs[ldk + 2][ldr] = wv.z;
        Bs[ldk + 3][ldr] = wv.w;
        __syncthreads();

#pragma unroll
        for (int k = 0; k < 16; k++) {
            float4 a = *reinterpret_cast<const float4*>(&As[k][tm * 4]);
            float4 b = *reinterpret_cast<const float4*>(&Bs[k][tn * 4]);
            acc[0][0] += a.x * b.x; acc[0][1] += a.x * b.y; acc[0][2] += a.x * b.z; acc[0][3] += a.x * b.w;
            acc[1][0] += a.y * b.x; acc[1][1] += a.y * b.y; acc[1][2] += a.y * b.z; acc[1][3] += a.y * b.w;
            acc[2][0] += a.z * b.x; acc[2][1] += a.z * b.y; acc[2][2] += a.z * b.z; acc[2][3] += a.z * b.w;
            acc[3][0] += a.w * b.x; acc[3][1] += a.w * b.y; acc[3][2] += a.w * b.z; acc[3][3] += a.w * b.w;
        }
        __syncthreads();
    }

    const int gcol = col0 + tn * 4;
    float4 bias4 = *reinterpret_cast<const float4*>(&bptr[gcol]);
#pragma unroll
    for (int i = 0; i < 4; i++) {
        int grow = row0 + tm * 4 + i;
        float4 v;
        v.x = acc[i][0] + bias4.x;
        v.y = acc[i][1] + bias4.y;
        v.z = acc[i][2] + bias4.z;
        v.w = acc[i][3] + bias4.w;
        if (doRelu) {
            v.x = fmaxf(v.x, 0.0f);
            v.y = fmaxf(v.y, 0.0f);
            v.z = fmaxf(v.z, 0.0f);
            v.w = fmaxf(v.w, 0.0f);
        }
        *reinterpret_cast<float4*>(&C[(size_t)grow * Nn + gcol]) = v;
    }
}

// ---------------- deterministic segment mean (parallel scan version) ----------------
// One block per node. All 2048 edge node-ids are staged in shared memory once
// (coalesced; L2-resident across blocks). Each of the 8 warps scans a 256-edge
// chunk with ballot; a cross-warp prefix assigns globally ascending positions,
// so the summation order is exactly ascending edge index -> deterministic and
// identical to the previous version. Then 256 threads (one per feature) reduce.
__global__ __launch_bounds__(256) void segment_kernel(const int* __restrict__ src,
                                                      const int* __restrict__ tgt) {
    __shared__ int s_ids[2 * BB];
    __shared__ int s_list[2 * BB];
    __shared__ int s_wbase[8];
    __shared__ int s_total;
    const int n   = blockIdx.x;
    const int tid = threadIdx.x;
    const int wid = tid >> 5;
    const int lid = tid & 31;

    // stage all edge node ids in shared (coalesced)
#pragma unroll
    for (int i = 0; i < 8; i++) {
        int e = tid + i * 256;
        s_ids[e] = (e < BB) ? src[e] : tgt[e - BB];
    }
    __syncthreads();

    const int chunk0 = wid * 256;

    // pass 1: per-warp match count
    int cnt = 0;
#pragma unroll
    for (int r = 0; r < 8; r++) {
        int e = chunk0 + r * 32 + lid;
        unsigned m = __ballot_sync(0xffffffffu, s_ids[e] == n);
        cnt += __popc(m);
    }
    if (lid == 0) s_wbase[wid] = cnt;
    __syncthreads();

    // prefix over 8 warps (single thread; trivial)
    if (tid == 0) {
        int acc = 0;
#pragma unroll
        for (int w = 0; w < 8; w++) {
            int c = s_wbase[w];
            s_wbase[w] = acc;
            acc += c;
        }
        s_total = acc;
    }
    __syncthreads();

    // pass 2: write ordered edge list (ascending edge index overall)
    int base = s_wbase[wid];
#pragma unroll
    for (int r = 0; r < 8; r++) {
        int e = chunk0 + r * 32 + lid;
        bool hit = (s_ids[e] == n);
        unsigned m = __ballot_sync(0xffffffffu, hit);
        if (hit) s_list[base + __popc(m & ((1u << lid) - 1u))] = e;
        base += __popc(m);
    }
    __syncthreads();

    // reduce messages in deterministic order
    const int total = s_total;
    float sum = 0.0f;
    for (int i = 0; i < total; i++) {
        int e = s_list[i];
        sum += g_MSG[(size_t)e * DD + tid];
    }
    float denom = (total > 0) ? (float)total : 1.0f;
    g_AGG[(size_t)n * DD + tid] = sum / denom;
    if (tid == 0) g_CNT[n] = total;
}

// ---------------- GRU gates + masked write ----------------
__global__ void gate_kernel(const float* __restrict__ memory,
                            float* __restrict__ out) {
    const int n = blockIdx.x;
    const int d = threadIdx.x;
    const float* gi = g_G + (size_t)n * K3;
    const float* gh = g_G + (size_t)(NN + n) * K3;

    float r  = 1.0f / (1.0f + expf(-(gi[d] + gh[d])));
    float z  = 1.0f / (1.0f + expf(-(gi[DD + d] + gh[DD + d])));
    float nn = tanhf(gi[2 * DD + d] + r * gh[2 * DD + d]);
    float h  = memory[(size_t)n * DD + d];
    float nv = (1.0f - z) * nn + z * h;
    out[(size_t)n * DD + d] = (g_CNT[n] > 0) ? nv : h;
}

// ---------------- launch ----------------
extern "C" void kernel_launch(void* const* d_in, const int* in_sizes, int n_in,
                              void* d_out, int out_size) {
    const float* memory  = (const float*)d_in[0];
    const int*   source  = (const int*)d_in[1];
    const int*   target  = (const int*)d_in[2];
    const float* dtv     = (const float*)d_in[3];
    const float* src_w1  = (const float*)d_in[4];
    const float* src_b1  = (const float*)d_in[5];
    const float* src_w2  = (const float*)d_in[6];
    const float* src_b2  = (const float*)d_in[7];
    const float* tar_w1  = (const float*)d_in[8];
    const float* tar_b1  = (const float*)d_in[9];
    const float* tar_w2  = (const float*)d_in[10];
    const float* tar_b2  = (const float*)d_in[11];
    const float* gru_wih = (const float*)d_in[12];
    const float* gru_whh = (const float*)d_in[13];
    const float* gru_bih = (const float*)d_in[14];
    const float* gru_bhh = (const float*)d_in[15];
    float* out = (float*)d_out;

    float *pX, *pH, *pMSG, *pAGG, *pG;
    cudaGetSymbolAddress((void**)&pX,   g_X);
    cudaGetSymbolAddress((void**)&pH,   g_H);
    cudaGetSymbolAddress((void**)&pMSG, g_MSG);
    cudaGetSymbolAddress((void**)&pAGG, g_AGG);
    cudaGetSymbolAddress((void**)&pG,   g_G);

    // 1) gather concat inputs
    gather_kernel<<<BB, DD>>>(memory, source, target, dtv);

    // 2) MLP layer 1 (relu): X[2048,768] -> H[2048,256]
    gemm_kernel<<<dim3(DD / 64, (2 * BB) / 64), 256>>>(
        pX, pX + (size_t)BB * K3, src_w1, tar_w1, src_b1, tar_b1,
        pH, BB, DD, K3, 1);

    // 3) MLP layer 2: H[2048,256] -> MSG[2048,256]
    gemm_kernel<<<dim3(DD / 64, (2 * BB) / 64), 256>>>(
        pH, pH + (size_t)BB * DD, src_w2, tar_w2, src_b2, tar_b2,
        pMSG, BB, DD, DD, 0);

    // 4) deterministic segment mean -> AGG[1024,256], CNT
    segment_kernel<<<NN, 256>>>(source, target);

    // 5) GRU preactivations: gi = agg@wih^T + bih ; gh = memory@whh^T + bhh
    gemm_kernel<<<dim3(K3 / 64, (2 * NN) / 64), 256>>>(
        pAGG, memory, gru_wih, gru_whh, gru_bih, gru_bhh,
        pG, NN, K3, DD, 0);

    // 6) gates + masked output
    gate_kernel<<<NN, DD>>>(memory, out);
}

// round 8
// speedup vs baseline: 1.5493x; 1.4102x over previous
#include <cuda_runtime.h>
#include <cuda_bf16.h>
#include <math.h>
#include <stdint.h>

// Problem constants
#define BB 1024   // batch (edges per direction)
#define NN 1024   // nodes
#define DD 256    // feature dim
#define K3 768    // 3*D

// ---------------- static scratch (no allocations allowed) ----------------
__device__ __nv_bfloat16 g_Xh[2 * BB * K3], g_Xl[2 * BB * K3];   // MLP inputs hi/lo
__device__ __nv_bfloat16 g_Hh[2 * BB * DD], g_Hl[2 * BB * DD];   // hidden hi/lo
__device__ float         g_MSG[2 * BB * DD];                     // messages fp32
__device__ __nv_bfloat16 g_AGGh[NN * DD], g_AGGl[NN * DD];       // segment mean hi/lo
__device__ __nv_bfloat16 g_Mh[NN * DD], g_Ml[NN * DD];           // memory hi/lo
__device__ float         g_G[2 * NN * K3];                       // gi | gh fp32
__device__ int           g_CNT[NN];
__device__ __nv_bfloat16 g_W1h[2 * DD * K3], g_W1l[2 * DD * K3]; // [src|tar] w1
__device__ __nv_bfloat16 g_W2h[2 * DD * DD], g_W2l[2 * DD * DD]; // [src|tar] w2
__device__ __nv_bfloat16 g_WGh[2 * K3 * DD], g_WGl[2 * K3 * DD]; // [wih|whh]

// ---------------- fp32 -> bf16 hi/lo split ----------------
__device__ __forceinline__ void split_bf16(float v, __nv_bfloat16& h, __nv_bfloat16& l) {
    h = __float2bfloat16(v);
    l = __float2bfloat16(v - __bfloat162float(h));
}

__global__ void convert_kernel(const float* __restrict__ x,
                               __nv_bfloat16* __restrict__ h,
                               __nv_bfloat16* __restrict__ l, int n) {
    int i = blockIdx.x * 256 + threadIdx.x;
    if (i < n) {
        __nv_bfloat16 hb, lb;
        split_bf16(x[i], hb, lb);
        h[i] = hb;
        l[i] = lb;
    }
}

// ---------------- gather: build concat inputs (bf16 hi/lo) ----------------
__global__ void gather_kernel(const float* __restrict__ memory,
                              const int* __restrict__ src,
                              const int* __restrict__ tgt,
                              const float* __restrict__ dtv) {
    int b = blockIdx.x;
    int d = threadIdx.x;
    int s = src[b];
    int t = tgt[b];
    float ms = memory[(size_t)s * DD + d];
    float mt = memory[(size_t)t * DD + d];
    float ds = dtv[((size_t)b * NN + s) * DD + d];
    float dt = dtv[((size_t)b * NN + t) * DD + d];
    size_t rs = (size_t)b * K3;
    size_t rt = (size_t)(BB + b) * K3;
    __nv_bfloat16 h, l;
    split_bf16(ms, h, l); g_Xh[rs + d] = h;          g_Xl[rs + d] = l;
    split_bf16(mt, h, l); g_Xh[rs + DD + d] = h;     g_Xl[rs + DD + d] = l;
    split_bf16(ds, h, l); g_Xh[rs + 2*DD + d] = h;   g_Xl[rs + 2*DD + d] = l;
    split_bf16(mt, h, l); g_Xh[rt + d] = h;          g_Xl[rt + d] = l;
    split_bf16(ms, h, l); g_Xh[rt + DD + d] = h;     g_Xl[rt + DD + d] = l;
    split_bf16(dt, h, l); g_Xh[rt + 2*DD + d] = h;   g_Xl[rt + 2*DD + d] = l;
}

// ---------------- mma.sync bf16 helper ----------------
__device__ __forceinline__ void mma_bf16(float* c, const uint32_t* a, const uint32_t* b) {
    asm volatile(
        "mma.sync.aligned.m16n8k16.row.col.f32.bf16.bf16.f32 "
        "{%0,%1,%2,%3}, {%4,%5,%6,%7}, {%8,%9}, {%0,%1,%2,%3};\n"
        : "+f"(c[0]), "+f"(c[1]), "+f"(c[2]), "+f"(c[3])
        : "r"(a[0]), "r"(a[1]), "r"(a[2]), "r"(a[3]), "r"(b[0]), "r"(b[1]));
}

// ---------------- tensor-core dual-half GEMM (mma.sync, 3-term bf16 split) ----
// C[m,n] = act( sum_k A[m,k]*W[n,k] + bias[n] ), A=Ahi+Alo, W=Whi+Wlo.
// rows [0,halfM) use operand set 0, rows [halfM,2*halfM) use set 1.
// Block tile 64x64, BK=32, 8 warps in 2(m) x 4(n) grid, warp tile 32x16.
// SMEM rows padded to 40 bf16 so fragment LDS (word = gid*20 + tig) is
// conflict-free across all 32 lanes.
#define SPAD 40

__global__ __launch_bounds__(256) void tgemm_kernel(
    const __nv_bfloat16* __restrict__ Ah0, const __nv_bfloat16* __restrict__ Al0,
    const __nv_bfloat16* __restrict__ Ah1, const __nv_bfloat16* __restrict__ Al1,
    const __nv_bfloat16* __restrict__ Wh0, const __nv_bfloat16* __restrict__ Wl0,
    const __nv_bfloat16* __restrict__ Wh1, const __nv_bfloat16* __restrict__ Wl1,
    const float* __restrict__ b0, const float* __restrict__ b1,
    float* __restrict__ Cf, __nv_bfloat16* __restrict__ Chi, __nv_bfloat16* __restrict__ Clo,
    int halfM, int Nn, int Kk, int doRelu) {

    __shared__ __align__(16) __nv_bfloat16 sAh[64 * SPAD];
    __shared__ __align__(16) __nv_bfloat16 sAl[64 * SPAD];
    __shared__ __align__(16) __nv_bfloat16 sWh[64 * SPAD];
    __shared__ __align__(16) __nv_bfloat16 sWl[64 * SPAD];

    const int tid  = threadIdx.x;
    const int wid  = tid >> 5;
    const int lane = tid & 31;
    const int gid  = lane >> 2;   // 0..7
    const int tig  = lane & 3;    // 0..3

    const int row0 = blockIdx.y * 64;
    const int col0 = blockIdx.x * 64;
    const bool hi2 = (row0 >= halfM);
    const __nv_bfloat16* __restrict__ Ah = hi2 ? Ah1 : Ah0;
    const __nv_bfloat16* __restrict__ Al = hi2 ? Al1 : Al0;
    const __nv_bfloat16* __restrict__ Wh = hi2 ? Wh1 : Wh0;
    const __nv_bfloat16* __restrict__ Wl = hi2 ? Wl1 : Wl0;
    const float* __restrict__ bias = hi2 ? b1 : b0;
    const int arow0 = row0 - (hi2 ? halfM : 0);

    const int warp_m = wid >> 2;  // 0..1
    const int warp_n = wid & 3;   // 0..3

    float acc[2][2][4];
#pragma unroll
    for (int mi = 0; mi < 2; mi++)
#pragma unroll
        for (int ni = 0; ni < 2; ni++)
#pragma unroll
            for (int j = 0; j < 4; j++) acc[mi][ni][j] = 0.0f;

    const int lr = tid >> 2;          // load row 0..63
    const int lk = (tid & 3) * 8;     // load k offset 0,8,16,24

    for (int kt = 0; kt < Kk; kt += 32) {
        // ---- stage tiles ----
        {
            const uint4 va = *reinterpret_cast<const uint4*>(&Ah[(size_t)(arow0 + lr) * Kk + kt + lk]);
            const uint4 vb = *reinterpret_cast<const uint4*>(&Al[(size_t)(arow0 + lr) * Kk + kt + lk]);
            const uint4 vc = *reinterpret_cast<const uint4*>(&Wh[(size_t)(col0 + lr) * Kk + kt + lk]);
            const uint4 vd = *reinterpret_cast<const uint4*>(&Wl[(size_t)(col0 + lr) * Kk + kt + lk]);
            *reinterpret_cast<uint4*>(&sAh[lr * SPAD + lk]) = va;
            *reinterpret_cast<uint4*>(&sAl[lr * SPAD + lk]) = vb;
            *reinterpret_cast<uint4*>(&sWh[lr * SPAD + lk]) = vc;
            *reinterpret_cast<uint4*>(&sWl[lr * SPAD + lk]) = vd;
        }
        __syncthreads();

        // ---- compute ----
#pragma unroll
        for (int ks = 0; ks < 2; ks++) {
            const int kk = ks * 16 + tig * 2;
            uint32_t ah[2][4], al[2][4];
#pragma unroll
            for (int mi = 0; mi < 2; mi++) {
                const int rb = warp_m * 32 + mi * 16;
                ah[mi][0] = *reinterpret_cast<const uint32_t*>(&sAh[(rb + gid) * SPAD + kk]);
                ah[mi][1] = *reinterpret_cast<const uint32_t*>(&sAh[(rb + gid + 8) * SPAD + kk]);
                ah[mi][2] = *reinterpret_cast<const uint32_t*>(&sAh[(rb + gid) * SPAD + kk + 8]);
                ah[mi][3] = *reinterpret_cast<const uint32_t*>(&sAh[(rb + gid + 8) * SPAD + kk + 8]);
                al[mi][0] = *reinterpret_cast<const uint32_t*>(&sAl[(rb + gid) * SPAD + kk]);
                al[mi][1] = *reinterpret_cast<const uint32_t*>(&sAl[(rb + gid + 8) * SPAD + kk]);
                al[mi][2] = *reinterpret_cast<const uint32_t*>(&sAl[(rb + gid) * SPAD + kk + 8]);
                al[mi][3] = *reinterpret_cast<const uint32_t*>(&sAl[(rb + gid + 8) * SPAD + kk + 8]);
            }
            uint32_t bh[2][2], bl[2][2];
#pragma unroll
            for (int ni = 0; ni < 2; ni++) {
                const int nr = warp_n * 16 + ni * 8 + gid;
                bh[ni][0] = *reinterpret_cast<const uint32_t*>(&sWh[nr * SPAD + kk]);
                bh[ni][1] = *reinterpret_cast<const uint32_t*>(&sWh[nr * SPAD + kk + 8]);
                bl[ni][0] = *reinterpret_cast<const uint32_t*>(&sWl[nr * SPAD + kk]);
                bl[ni][1] = *reinterpret_cast<const uint32_t*>(&sWl[nr * SPAD + kk + 8]);
            }
#pragma unroll
            for (int mi = 0; mi < 2; mi++)
#pragma unroll
                for (int ni = 0; ni < 2; ni++) {
                    mma_bf16(acc[mi][ni], ah[mi], bh[ni]);
                    mma_bf16(acc[mi][ni], ah[mi], bl[ni]);
                    mma_bf16(acc[mi][ni], al[mi], bh[ni]);
                }
        }
        __syncthreads();
    }

    // ---- epilogue: bias + activation + stores ----
#pragma unroll
    for (int mi = 0; mi < 2; mi++) {
#pragma unroll
        for (int ni = 0; ni < 2; ni++) {
            const int r0 = row0 + warp_m * 32 + mi * 16 + gid;
            const int c  = col0 + warp_n * 16 + ni * 8 + tig * 2;
            const float bx = bias[c];
            const float by = bias[c + 1];
            float v0 = acc[mi][ni][0] + bx;
            float v1 = acc[mi][ni][1] + by;
            float v2 = acc[mi][ni][2] + bx;
            float v3 = acc[mi][ni][3] + by;
            if (doRelu) {
                v0 = fmaxf(v0, 0.0f); v1 = fmaxf(v1, 0.0f);
                v2 = fmaxf(v2, 0.0f); v3 = fmaxf(v3, 0.0f);
            }
            if (Cf) {
                *reinterpret_cast<float2*>(&Cf[(size_t)r0 * Nn + c])       = make_float2(v0, v1);
                *reinterpret_cast<float2*>(&Cf[(size_t)(r0 + 8) * Nn + c]) = make_float2(v2, v3);
            }
            if (Chi) {
                __nv_bfloat16 h0, l0, h1, l1;
                split_bf16(v0, h0, l0); split_bf16(v1, h1, l1);
                __nv_bfloat162 hp; hp.x = h0; hp.y = h1;
                __nv_bfloat162 lp; lp.x = l0; lp.y = l1;
                *reinterpret_cast<__nv_bfloat162*>(&Chi[(size_t)r0 * Nn + c]) = hp;
                *reinterpret_cast<__nv_bfloat162*>(&Clo[(size_t)r0 * Nn + c]) = lp;
                split_bf16(v2, h0, l0); split_bf16(v3, h1, l1);
                hp.x = h0; hp.y = h1;
                lp.x = l0; lp.y = l1;
                *reinterpret_cast<__nv_bfloat162*>(&Chi[(size_t)(r0 + 8) * Nn + c]) = hp;
                *reinterpret_cast<__nv_bfloat162*>(&Clo[(size_t)(r0 + 8) * Nn + c]) = lp;
            }
        }
    }
}

// ---------------- deterministic segment mean (parallel scan) ----------------
__global__ __launch_bounds__(256) void segment_kernel(const int* __restrict__ src,
                                                      const int* __restrict__ tgt) {
    __shared__ int s_ids[2 * BB];
    __shared__ int s_list[2 * BB];
    __shared__ int s_wbase[8];
    __shared__ int s_total;
    const int n   = blockIdx.x;
    const int tid = threadIdx.x;
    const int wid = tid >> 5;
    const int lid = tid & 31;

#pragma unroll
    for (int i = 0; i < 8; i++) {
        int e = tid + i * 256;
        s_ids[e] = (e < BB) ? src[e] : tgt[e - BB];
    }
    __syncthreads();

    const int chunk0 = wid * 256;
    int cnt = 0;
#pragma unroll
    for (int r = 0; r < 8; r++) {
        int e = chunk0 + r * 32 + lid;
        unsigned m = __ballot_sync(0xffffffffu, s_ids[e] == n);
        cnt += __popc(m);
    }
    if (lid == 0) s_wbase[wid] = cnt;
    __syncthreads();

    if (tid == 0) {
        int acc = 0;
#pragma unroll
        for (int w = 0; w < 8; w++) { int c = s_wbase[w]; s_wbase[w] = acc; acc += c; }
        s_total = acc;
    }
    __syncthreads();

    int base = s_wbase[wid];
#pragma unroll
    for (int r = 0; r < 8; r++) {
        int e = chunk0 + r * 32 + lid;
        bool hit = (s_ids[e] == n);
        unsigned m = __ballot_sync(0xffffffffu, hit);
        if (hit) s_list[base + __popc(m & ((1u << lid) - 1u))] = e;
        base += __popc(m);
    }
    __syncthreads();

    const int total = s_total;
    float sum = 0.0f;
    for (int i = 0; i < total; i++) {
        int e = s_list[i];
        sum += g_MSG[(size_t)e * DD + tid];
    }
    float denom = (total > 0) ? (float)total : 1.0f;
    float mean = sum / denom;
    __nv_bfloat16 h, l;
    split_bf16(mean, h, l);
    g_AGGh[(size_t)n * DD + tid] = h;
    g_AGGl[(size_t)n * DD + tid] = l;
    if (tid == 0) g_CNT[n] = total;
}

// ---------------- GRU gates + masked write ----------------
__global__ void gate_kernel(const float* __restrict__ memory,
                            float* __restrict__ out) {
    const int n = blockIdx.x;
    const int d = threadIdx.x;
    const float* gi = g_G + (size_t)n * K3;
    const float* gh = g_G + (size_t)(NN + n) * K3;

    float r  = 1.0f / (1.0f + expf(-(gi[d] + gh[d])));
    float z  = 1.0f / (1.0f + expf(-(gi[DD + d] + gh[DD + d])));
    float nn = tanhf(gi[2 * DD + d] + r * gh[2 * DD + d]);
    float h  = memory[(size_t)n * DD + d];
    float nv = (1.0f - z) * nn + z * h;
    out[(size_t)n * DD + d] = (g_CNT[n] > 0) ? nv : h;
}

// ---------------- launch ----------------
extern "C" void kernel_launch(void* const* d_in, const int* in_sizes, int n_in,
                              void* d_out, int out_size) {
    const float* memory  = (const float*)d_in[0];
    const int*   source  = (const int*)d_in[1];
    const int*   target  = (const int*)d_in[2];
    const float* dtv     = (const float*)d_in[3];
    const float* src_w1  = (const float*)d_in[4];
    const float* src_b1  = (const float*)d_in[5];
    const float* src_w2  = (const float*)d_in[6];
    const float* src_b2  = (const float*)d_in[7];
    const float* tar_w1  = (const float*)d_in[8];
    const float* tar_b1  = (const float*)d_in[9];
    const float* tar_w2  = (const float*)d_in[10];
    const float* tar_b2  = (const float*)d_in[11];
    const float* gru_wih = (const float*)d_in[12];
    const float* gru_whh = (const float*)d_in[13];
    const float* gru_bih = (const float*)d_in[14];
    const float* gru_bhh = (const float*)d_in[15];
    float* out = (float*)d_out;

    __nv_bfloat16 *pXh, *pXl, *pHh, *pHl, *pAGGh, *pAGGl, *pMh, *pMl;
    __nv_bfloat16 *pW1h, *pW1l, *pW2h, *pW2l, *pWGh, *pWGl;
    float *pMSG, *pG;
    cudaGetSymbolAddress((void**)&pXh, g_Xh);   cudaGetSymbolAddress((void**)&pXl, g_Xl);
    cudaGetSymbolAddress((void**)&pHh, g_Hh);   cudaGetSymbolAddress((void**)&pHl, g_Hl);
    cudaGetSymbolAddress((void**)&pAGGh, g_AGGh); cudaGetSymbolAddress((void**)&pAGGl, g_AGGl);
    cudaGetSymbolAddress((void**)&pMh, g_Mh);   cudaGetSymbolAddress((void**)&pMl, g_Ml);
    cudaGetSymbolAddress((void**)&pW1h, g_W1h); cudaGetSymbolAddress((void**)&pW1l, g_W1l);
    cudaGetSymbolAddress((void**)&pW2h, g_W2h); cudaGetSymbolAddress((void**)&pW2l, g_W2l);
    cudaGetSymbolAddress((void**)&pWGh, g_WGh); cudaGetSymbolAddress((void**)&pWGl, g_WGl);
    cudaGetSymbolAddress((void**)&pMSG, g_MSG); cudaGetSymbolAddress((void**)&pG, g_G);

    // 0) convert weights + memory to bf16 hi/lo
    const int nW1 = DD * K3, nW2 = DD * DD, nWG = K3 * DD, nM = NN * DD;
    convert_kernel<<<(nW1 + 255) / 256, 256>>>(src_w1, pW1h, pW1l, nW1);
    convert_kernel<<<(nW1 + 255) / 256, 256>>>(tar_w1, pW1h + nW1, pW1l + nW1, nW1);
    convert_kernel<<<(nW2 + 255) / 256, 256>>>(src_w2, pW2h, pW2l, nW2);
    convert_kernel<<<(nW2 + 255) / 256, 256>>>(tar_w2, pW2h + nW2, pW2l + nW2, nW2);
    convert_kernel<<<(nWG + 255) / 256, 256>>>(gru_wih, pWGh, pWGl, nWG);
    convert_kernel<<<(nWG + 255) / 256, 256>>>(gru_whh, pWGh + nWG, pWGl + nWG, nWG);
    convert_kernel<<<(nM + 255) / 256, 256>>>(memory, pMh, pMl, nM);

    // 1) gather concat inputs (bf16 hi/lo)
    gather_kernel<<<BB, DD>>>(memory, source, target, dtv);

    // 2) MLP layer 1 (relu): X[2048,768] -> H[2048,256] (bf16 hi/lo out)
    tgemm_kernel<<<dim3(DD / 64, (2 * BB) / 64), 256>>>(
        pXh, pXl, pXh + (size_t)BB * K3, pXl + (size_t)BB * K3,
        pW1h, pW1l, pW1h + nW1, pW1l + nW1,
        src_b1, tar_b1, nullptr, pHh, pHl, BB, DD, K3, 1);

    // 3) MLP layer 2: H[2048,256] -> MSG[2048,256] fp32
    tgemm_kernel<<<dim3(DD / 64, (2 * BB) / 64), 256>>>(
        pHh, pHl, pHh + (size_t)BB * DD, pHl + (size_t)BB * DD,
        pW2h, pW2l, pW2h + nW2, pW2l + nW2,
        src_b2, tar_b2, pMSG, nullptr, nullptr, BB, DD, DD, 0);

    // 4) deterministic segment mean -> AGG hi/lo, CNT
    segment_kernel<<<NN, 256>>>(source, target);

    // 5) GRU preactivations: gi = agg@wih^T + bih ; gh = memory@whh^T + bhh
    tgemm_kernel<<<dim3(K3 / 64, (2 * NN) / 64), 256>>>(
        pAGGh, pAGGl, pMh, pMl,
        pWGh, pWGl, pWGh + nWG, pWGl + nWG,
        gru_bih, gru_bhh, pG, nullptr, nullptr, NN, K3, DD, 0);

    // 6) gates + masked output
    gate_kernel<<<NN, DD>>>(memory, out);
}

// round 9
// speedup vs baseline: 1.6976x; 1.0957x over previous
#include <cuda_runtime.h>
#include <cuda_bf16.h>
#include <math.h>
#include <stdint.h>

// Problem constants
#define BB 1024   // batch (edges per direction)
#define NN 1024   // nodes
#define DD 256    // feature dim
#define K3 768    // 3*D

// ---------------- static scratch (no allocations allowed) ----------------
__device__ __nv_bfloat16 g_Xh[2 * BB * K3], g_Xl[2 * BB * K3];   // MLP inputs hi/lo
__device__ __nv_bfloat16 g_Hh[2 * BB * DD], g_Hl[2 * BB * DD];   // hidden hi/lo
__device__ float         g_MSG[2 * BB * DD];                     // messages fp32
__device__ __nv_bfloat16 g_AGGh[NN * DD], g_AGGl[NN * DD];       // segment mean hi/lo
__device__ float         g_G[2 * NN * K3];                       // gi | gh fp32
__device__ int           g_CNT[NN];

// ---------------- fp32 -> bf16 hi/lo split ----------------
__device__ __forceinline__ void split_bf16(float v, __nv_bfloat16& h, __nv_bfloat16& l) {
    h = __float2bfloat16(v);
    l = __float2bfloat16(v - __bfloat162float(h));
}
__device__ __forceinline__ uint32_t pack2(__nv_bfloat16 a, __nv_bfloat16 b) {
    __nv_bfloat162 t; t.x = a; t.y = b;
    return *reinterpret_cast<uint32_t*>(&t);
}

// ---------------- gather: build concat inputs (bf16 hi/lo) ----------------
__global__ void gather_kernel(const float* __restrict__ memory,
                              const int* __restrict__ src,
                              const int* __restrict__ tgt,
                              const float* __restrict__ dtv) {
    int b = blockIdx.x;
    int d = threadIdx.x;
    int s = src[b];
    int t = tgt[b];
    float ms = memory[(size_t)s * DD + d];
    float mt = memory[(size_t)t * DD + d];
    float ds = dtv[((size_t)b * NN + s) * DD + d];
    float dt = dtv[((size_t)b * NN + t) * DD + d];
    size_t rs = (size_t)b * K3;
    size_t rt = (size_t)(BB + b) * K3;
    __nv_bfloat16 h, l;
    split_bf16(ms, h, l); g_Xh[rs + d] = h;          g_Xl[rs + d] = l;
    split_bf16(mt, h, l); g_Xh[rs + DD + d] = h;     g_Xl[rs + DD + d] = l;
    split_bf16(ds, h, l); g_Xh[rs + 2*DD + d] = h;   g_Xl[rs + 2*DD + d] = l;
    split_bf16(mt, h, l); g_Xh[rt + d] = h;          g_Xl[rt + d] = l;
    split_bf16(ms, h, l); g_Xh[rt + DD + d] = h;     g_Xl[rt + DD + d] = l;
    split_bf16(dt, h, l); g_Xh[rt + 2*DD + d] = h;   g_Xl[rt + 2*DD + d] = l;
}

// ---------------- mma.sync bf16 helper ----------------
__device__ __forceinline__ void mma_bf16(float* c, const uint32_t* a, const uint32_t* b) {
    asm volatile(
        "mma.sync.aligned.m16n8k16.row.col.f32.bf16.bf16.f32 "
        "{%0,%1,%2,%3}, {%4,%5,%6,%7}, {%8,%9}, {%0,%1,%2,%3};\n"
        : "+f"(c[0]), "+f"(c[1]), "+f"(c[2]), "+f"(c[3])
        : "r"(a[0]), "r"(a[1]), "r"(a[2]), "r"(a[3]), "r"(b[0]), "r"(b[1]));
}

// ---------------- tensor-core dual-half GEMM (mma.sync, 3-term bf16 split) ----
// C[m,n] = act( sum_k A[m,k]*W[n,k] + bias[n] ), operands bf16 hi/lo pairs.
// Sources per operand-half: EITHER a pre-split bf16 (h,l) pair OR an fp32
// pointer split on the fly during staging (fp32 wins when non-null).
// Block tile 64x64, BK=32, 8 warps in 2(m) x 4(n) grid, warp tile 32x16.
// SMEM rows padded to 40 bf16 so fragment LDS is conflict-free.
#define SPAD 40

// stage one 64x32 tile (hi+lo) from either source form; thread handles 8 elems
__device__ __forceinline__ void stage_tile(
    __nv_bfloat16* sh, __nv_bfloat16* sl,
    const __nv_bfloat16* __restrict__ gh, const __nv_bfloat16* __restrict__ gl,
    const float* __restrict__ gf,
    int grow0, int ld, int kt, int lr, int lk) {
    if (gf) {
        const float* p = &gf[(size_t)(grow0 + lr) * ld + kt + lk];
        float4 f0 = *reinterpret_cast<const float4*>(p);
        float4 f1 = *reinterpret_cast<const float4*>(p + 4);
        __nv_bfloat16 h0,l0,h1,l1,h2,l2,h3,l3,h4,l4,h5,l5,h6,l6,h7,l7;
        split_bf16(f0.x, h0, l0); split_bf16(f0.y, h1, l1);
        split_bf16(f0.z, h2, l2); split_bf16(f0.w, h3, l3);
        split_bf16(f1.x, h4, l4); split_bf16(f1.y, h5, l5);
        split_bf16(f1.z, h6, l6); split_bf16(f1.w, h7, l7);
        uint4 vh = make_uint4(pack2(h0,h1), pack2(h2,h3), pack2(h4,h5), pack2(h6,h7));
        uint4 vl = make_uint4(pack2(l0,l1), pack2(l2,l3), pack2(l4,l5), pack2(l6,l7));
        *reinterpret_cast<uint4*>(&sh[lr * SPAD + lk]) = vh;
        *reinterpret_cast<uint4*>(&sl[lr * SPAD + lk]) = vl;
    } else {
        uint4 vh = *reinterpret_cast<const uint4*>(&gh[(size_t)(grow0 + lr) * ld + kt + lk]);
        uint4 vl = *reinterpret_cast<const uint4*>(&gl[(size_t)(grow0 + lr) * ld + kt + lk]);
        *reinterpret_cast<uint4*>(&sh[lr * SPAD + lk]) = vh;
        *reinterpret_cast<uint4*>(&sl[lr * SPAD + lk]) = vl;
    }
}

__global__ __launch_bounds__(256) void tgemm_kernel(
    const __nv_bfloat16* __restrict__ Ah0, const __nv_bfloat16* __restrict__ Al0,
    const float* __restrict__ Af0,
    const __nv_bfloat16* __restrict__ Ah1, const __nv_bfloat16* __restrict__ Al1,
    const float* __restrict__ Af1,
    const float* __restrict__ Wf0, const float* __restrict__ Wf1,
    const float* __restrict__ b0, const float* __restrict__ b1,
    float* __restrict__ Cf, __nv_bfloat16* __restrict__ Chi, __nv_bfloat16* __restrict__ Clo,
    int halfM, int Nn, int Kk, int doRelu) {

    __shared__ __align__(16) __nv_bfloat16 sAh[64 * SPAD];
    __shared__ __align__(16) __nv_bfloat16 sAl[64 * SPAD];
    __shared__ __align__(16) __nv_bfloat16 sWh[64 * SPAD];
    __shared__ __align__(16) __nv_bfloat16 sWl[64 * SPAD];

    const int tid  = threadIdx.x;
    const int wid  = tid >> 5;
    const int lane = tid & 31;
    const int gid  = lane >> 2;   // 0..7
    const int tig  = lane & 3;    // 0..3

    const int row0 = blockIdx.y * 64;
    const int col0 = blockIdx.x * 64;
    const bool hi2 = (row0 >= halfM);
    const __nv_bfloat16* __restrict__ Ah = hi2 ? Ah1 : Ah0;
    const __nv_bfloat16* __restrict__ Al = hi2 ? Al1 : Al0;
    const float* __restrict__ Af = hi2 ? Af1 : Af0;
    const float* __restrict__ Wf = hi2 ? Wf1 : Wf0;
    const float* __restrict__ bias = hi2 ? b1 : b0;
    const int arow0 = row0 - (hi2 ? halfM : 0);

    const int warp_m = wid >> 2;  // 0..1
    const int warp_n = wid & 3;   // 0..3

    float acc[2][2][4];
#pragma unroll
    for (int mi = 0; mi < 2; mi++)
#pragma unroll
        for (int ni = 0; ni < 2; ni++)
#pragma unroll
            for (int j = 0; j < 4; j++) acc[mi][ni][j] = 0.0f;

    const int lr = tid >> 2;          // load row 0..63
    const int lk = (tid & 3) * 8;     // load k offset 0,8,16,24

    for (int kt = 0; kt < Kk; kt += 32) {
        stage_tile(sAh, sAl, Ah, Al, Af, arow0, Kk, kt, lr, lk);
        stage_tile(sWh, sWl, nullptr, nullptr, Wf, col0, Kk, kt, lr, lk);
        __syncthreads();

#pragma unroll
        for (int ks = 0; ks < 2; ks++) {
            const int kk = ks * 16 + tig * 2;
            uint32_t ah[2][4], al[2][4];
#pragma unroll
            for (int mi = 0; mi < 2; mi++) {
                const int rb = warp_m * 32 + mi * 16;
                ah[mi][0] = *reinterpret_cast<const uint32_t*>(&sAh[(rb + gid) * SPAD + kk]);
                ah[mi][1] = *reinterpret_cast<const uint32_t*>(&sAh[(rb + gid + 8) * SPAD + kk]);
                ah[mi][2] = *reinterpret_cast<const uint32_t*>(&sAh[(rb + gid) * SPAD + kk + 8]);
                ah[mi][3] = *reinterpret_cast<const uint32_t*>(&sAh[(rb + gid + 8) * SPAD + kk + 8]);
                al[mi][0] = *reinterpret_cast<const uint32_t*>(&sAl[(rb + gid) * SPAD + kk]);
                al[mi][1] = *reinterpret_cast<const uint32_t*>(&sAl[(rb + gid + 8) * SPAD + kk]);
                al[mi][2] = *reinterpret_cast<const uint32_t*>(&sAl[(rb + gid) * SPAD + kk + 8]);
                al[mi][3] = *reinterpret_cast<const uint32_t*>(&sAl[(rb + gid + 8) * SPAD + kk + 8]);
            }
            uint32_t bh[2][2], bl[2][2];
#pragma unroll
            for (int ni = 0; ni < 2; ni++) {
                const int nr = warp_n * 16 + ni * 8 + gid;
                bh[ni][0] = *reinterpret_cast<const uint32_t*>(&sWh[nr * SPAD + kk]);
                bh[ni][1] = *reinterpret_cast<const uint32_t*>(&sWh[nr * SPAD + kk + 8]);
                bl[ni][0] = *reinterpret_cast<const uint32_t*>(&sWl[nr * SPAD + kk]);
                bl[ni][1] = *reinterpret_cast<const uint32_t*>(&sWl[nr * SPAD + kk + 8]);
            }
#pragma unroll
            for (int mi = 0; mi < 2; mi++)
#pragma unroll
                for (int ni = 0; ni < 2; ni++) {
                    mma_bf16(acc[mi][ni], ah[mi], bh[ni]);
                    mma_bf16(acc[mi][ni], ah[mi], bl[ni]);
                    mma_bf16(acc[mi][ni], al[mi], bh[ni]);
                }
        }
        __syncthreads();
    }

    // ---- epilogue: bias + activation + stores ----
#pragma unroll
    for (int mi = 0; mi < 2; mi++) {
#pragma unroll
        for (int ni = 0; ni < 2; ni++) {
            const int r0 = row0 + warp_m * 32 + mi * 16 + gid;
            const int c  = col0 + warp_n * 16 + ni * 8 + tig * 2;
            const float bx = bias[c];
            const float by = bias[c + 1];
            float v0 = acc[mi][ni][0] + bx;
            float v1 = acc[mi][ni][1] + by;
            float v2 = acc[mi][ni][2] + bx;
            float v3 = acc[mi][ni][3] + by;
            if (doRelu) {
                v0 = fmaxf(v0, 0.0f); v1 = fmaxf(v1, 0.0f);
                v2 = fmaxf(v2, 0.0f); v3 = fmaxf(v3, 0.0f);
            }
            if (Cf) {
                *reinterpret_cast<float2*>(&Cf[(size_t)r0 * Nn + c])       = make_float2(v0, v1);
                *reinterpret_cast<float2*>(&Cf[(size_t)(r0 + 8) * Nn + c]) = make_float2(v2, v3);
            }
            if (Chi) {
                __nv_bfloat16 h0, l0, h1, l1;
                split_bf16(v0, h0, l0); split_bf16(v1, h1, l1);
                *reinterpret_cast<uint32_t*>(&Chi[(size_t)r0 * Nn + c]) = pack2(h0, h1);
                *reinterpret_cast<uint32_t*>(&Clo[(size_t)r0 * Nn + c]) = pack2(l0, l1);
                split_bf16(v2, h0, l0); split_bf16(v3, h1, l1);
                *reinterpret_cast<uint32_t*>(&Chi[(size_t)(r0 + 8) * Nn + c]) = pack2(h0, h1);
                *reinterpret_cast<uint32_t*>(&Clo[(size_t)(r0 + 8) * Nn + c]) = pack2(l0, l1);
            }
        }
    }
}

// ---------------- deterministic segment mean (parallel scan) ----------------
__global__ __launch_bounds__(256) void segment_kernel(const int* __restrict__ src,
                                                      const int* __restrict__ tgt) {
    __shared__ int s_ids[2 * BB];
    __shared__ int s_list[2 * BB];
    __shared__ int s_wbase[8];
    __shared__ int s_total;
    const int n   = blockIdx.x;
    const int tid = threadIdx.x;
    const int wid = tid >> 5;
    const int lid = tid & 31;

#pragma unroll
    for (int i = 0; i < 8; i++) {
        int e = tid + i * 256;
        s_ids[e] = (e < BB) ? src[e] : tgt[e - BB];
    }
    __syncthreads();

    const int chunk0 = wid * 256;
    int cnt = 0;
#pragma unroll
    for (int r = 0; r < 8; r++) {
        int e = chunk0 + r * 32 + lid;
        unsigned m = __ballot_sync(0xffffffffu, s_ids[e] == n);
        cnt += __popc(m);
    }
    if (lid == 0) s_wbase[wid] = cnt;
    __syncthreads();

    if (tid == 0) {
        int acc = 0;
#pragma unroll
        for (int w = 0; w < 8; w++) { int c = s_wbase[w]; s_wbase[w] = acc; acc += c; }
        s_total = acc;
    }
    __syncthreads();

    int base = s_wbase[wid];
#pragma unroll
    for (int r = 0; r < 8; r++) {
        int e = chunk0 + r * 32 + lid;
        bool hit = (s_ids[e] == n);
        unsigned m = __ballot_sync(0xffffffffu, hit);
        if (hit) s_list[base + __popc(m & ((1u << lid) - 1u))] = e;
        base += __popc(m);
    }
    __syncthreads();

    const int total = s_total;
    float sum = 0.0f;
    for (int i = 0; i < total; i++) {
        int e = s_list[i];
        sum += g_MSG[(size_t)e * DD + tid];
    }
    float denom = (total > 0) ? (float)total : 1.0f;
    float mean = sum / denom;
    __nv_bfloat16 h, l;
    split_bf16(mean, h, l);
    g_AGGh[(size_t)n * DD + tid] = h;
    g_AGGl[(size_t)n * DD + tid] = l;
    if (tid == 0) g_CNT[n] = total;
}

// ---------------- GRU gates + masked write ----------------
__global__ void gate_kernel(const float* __restrict__ memory,
                            float* __restrict__ out) {
    const int n = blockIdx.x;
    const int d = threadIdx.x;
    const float* gi = g_G + (size_t)n * K3;
    const float* gh = g_G + (size_t)(NN + n) * K3;

    float r  = 1.0f / (1.0f + expf(-(gi[d] + gh[d])));
    float z  = 1.0f / (1.0f + expf(-(gi[DD + d] + gh[DD + d])));
    float nn = tanhf(gi[2 * DD + d] + r * gh[2 * DD + d]);
    float h  = memory[(size_t)n * DD + d];
    float nv = (1.0f - z) * nn + z * h;
    out[(size_t)n * DD + d] = (g_CNT[n] > 0) ? nv : h;
}

// ---------------- launch ----------------
extern "C" void kernel_launch(void* const* d_in, const int* in_sizes, int n_in,
                              void* d_out, int out_size) {
    const float* memory  = (const float*)d_in[0];
    const int*   source  = (const int*)d_in[1];
    const int*   target  = (const int*)d_in[2];
    const float* dtv     = (const float*)d_in[3];
    const float* src_w1  = (const float*)d_in[4];
    const float* src_b1  = (const float*)d_in[5];
    const float* src_w2  = (const float*)d_in[6];
    const float* src_b2  = (const float*)d_in[7];
    const float* tar_w1  = (const float*)d_in[8];
    const float* tar_b1  = (const float*)d_in[9];
    const float* tar_w2  = (const float*)d_in[10];
    const float* tar_b2  = (const float*)d_in[11];
    const float* gru_wih = (const float*)d_in[12];
    const float* gru_whh = (const float*)d_in[13];
    const float* gru_bih = (const float*)d_in[14];
    const float* gru_bhh = (const float*)d_in[15];
    float* out = (float*)d_out;

    __nv_bfloat16 *pXh, *pXl, *pHh, *pHl, *pAGGh, *pAGGl;
    float *pMSG, *pG;
    cudaGetSymbolAddress((void**)&pXh, g_Xh);   cudaGetSymbolAddress((void**)&pXl, g_Xl);
    cudaGetSymbolAddress((void**)&pHh, g_Hh);   cudaGetSymbolAddress((void**)&pHl, g_Hl);
    cudaGetSymbolAddress((void**)&pAGGh, g_AGGh); cudaGetSymbolAddress((void**)&pAGGl, g_AGGl);
    cudaGetSymbolAddress((void**)&pMSG, g_MSG); cudaGetSymbolAddress((void**)&pG, g_G);

    // 1) gather concat inputs (bf16 hi/lo)
    gather_kernel<<<BB, DD>>>(memory, source, target, dtv);

    // 2) MLP layer 1 (relu): X[2048,768] -> H[2048,256] (bf16 hi/lo out)
    //    A: pre-split bf16; W: fp32 split on the fly
    tgemm_kernel<<<dim3(DD / 64, (2 * BB) / 64), 256>>>(
        pXh, pXl, nullptr,
        pXh + (size_t)BB * K3, pXl + (size_t)BB * K3, nullptr,
        src_w1, tar_w1,
        src_b1, tar_b1, nullptr, pHh, pHl, BB, DD, K3, 1);

    // 3) MLP layer 2: H[2048,256] -> MSG[2048,256] fp32
    tgemm_kernel<<<dim3(DD / 64, (2 * BB) / 64), 256>>>(
        pHh, pHl, nullptr,
        pHh + (size_t)BB * DD, pHl + (size_t)BB * DD, nullptr,
        src_w2, tar_w2,
        src_b2, tar_b2, pMSG, nullptr, nullptr, BB, DD, DD, 0);

    // 4) deterministic segment mean -> AGG hi/lo, CNT
    segment_kernel<<<NN, 256>>>(source, target);

    // 5) GRU preactivations: gi = agg@wih^T + bih ; gh = memory@whh^T + bhh
    //    A0: AGG pre-split; A1: memory fp32 on the fly; W: fp32 on the fly
    tgemm_kernel<<<dim3(K3 / 64, (2 * NN) / 64), 256>>>(
        pAGGh, pAGGl, nullptr,
        nullptr, nullptr, memory,
        gru_wih, gru_whh,
        gru_bih, gru_bhh, pG, nullptr, nullptr, NN, K3, DD, 0);

    // 6) gates + masked output
    gate_kernel<<<NN, DD>>>(memory, out);
}

// round 10
// speedup vs baseline: 1.8496x; 1.0896x over previous
#include <cuda_runtime.h>
#include <cuda_bf16.h>
#include <math.h>
#include <stdint.h>

// Problem constants
#define BB 1024   // batch (edges per direction)
#define NN 1024   // nodes
#define DD 256    // feature dim
#define K3 768    // 3*D

// ---------------- static scratch (no allocations allowed) ----------------
__device__ __nv_bfloat16 g_Xh[2 * BB * K3], g_Xl[2 * BB * K3];   // MLP inputs hi/lo
__device__ __nv_bfloat16 g_Hh[2 * BB * DD], g_Hl[2 * BB * DD];   // hidden hi/lo
__device__ float         g_MSG[2 * BB * DD];                     // messages fp32
__device__ __nv_bfloat16 g_AGGh[NN * DD], g_AGGl[NN * DD];       // segment mean hi/lo
__device__ float         g_G[2 * NN * K3];                       // gi | gh fp32
__device__ int           g_CNT[NN];

// ---------------- fp32 -> bf16 hi/lo split ----------------
__device__ __forceinline__ void split_bf16(float v, __nv_bfloat16& h, __nv_bfloat16& l) {
    h = __float2bfloat16(v);
    l = __float2bfloat16(v - __bfloat162float(h));
}
__device__ __forceinline__ uint32_t pack2(__nv_bfloat16 a, __nv_bfloat16 b) {
    __nv_bfloat162 t; t.x = a; t.y = b;
    return *reinterpret_cast<uint32_t*>(&t);
}

// ---------------- gather: build concat inputs (bf16 hi/lo) ----------------
__global__ void gather_kernel(const float* __restrict__ memory,
                              const int* __restrict__ src,
                              const int* __restrict__ tgt,
                              const float* __restrict__ dtv) {
    int b = blockIdx.x;
    int d = threadIdx.x;
    int s = src[b];
    int t = tgt[b];
    float ms = memory[(size_t)s * DD + d];
    float mt = memory[(size_t)t * DD + d];
    float ds = dtv[((size_t)b * NN + s) * DD + d];
    float dt = dtv[((size_t)b * NN + t) * DD + d];
    size_t rs = (size_t)b * K3;
    size_t rt = (size_t)(BB + b) * K3;
    __nv_bfloat16 h, l;
    split_bf16(ms, h, l); g_Xh[rs + d] = h;          g_Xl[rs + d] = l;
    split_bf16(mt, h, l); g_Xh[rs + DD + d] = h;     g_Xl[rs + DD + d] = l;
    split_bf16(ds, h, l); g_Xh[rs + 2*DD + d] = h;   g_Xl[rs + 2*DD + d] = l;
    split_bf16(mt, h, l); g_Xh[rt + d] = h;          g_Xl[rt + d] = l;
    split_bf16(ms, h, l); g_Xh[rt + DD + d] = h;     g_Xl[rt + DD + d] = l;
    split_bf16(dt, h, l); g_Xh[rt + 2*DD + d] = h;   g_Xl[rt + 2*DD + d] = l;
}

// ---------------- mma.sync bf16 helper ----------------
__device__ __forceinline__ void mma_bf16(float* c, const uint32_t* a, const uint32_t* b) {
    asm volatile(
        "mma.sync.aligned.m16n8k16.row.col.f32.bf16.bf16.f32 "
        "{%0,%1,%2,%3}, {%4,%5,%6,%7}, {%8,%9}, {%0,%1,%2,%3};\n"
        : "+f"(c[0]), "+f"(c[1]), "+f"(c[2]), "+f"(c[3])
        : "r"(a[0]), "r"(a[1]), "r"(a[2]), "r"(a[3]), "r"(b[0]), "r"(b[1]));
}

// ---------------- tensor-core dual-half GEMM (mma.sync, 3-term bf16 split) ----
// Register-pipelined staging: LDGs for chunk c+1 issue before compute of chunk c.
#define SPAD 40

union LoadRegs {
    struct { uint4 vh, vl; } bf;
    struct { float4 f0, f1; } fp;
};

__device__ __forceinline__ void load_regs(
    LoadRegs& r,
    const __nv_bfloat16* __restrict__ gh, const __nv_bfloat16* __restrict__ gl,
    const float* __restrict__ gf,
    int grow0, int ld, int kt, int lr, int lk) {
    if (gf) {
        const float* p = &gf[(size_t)(grow0 + lr) * ld + kt + lk];
        r.fp.f0 = *reinterpret_cast<const float4*>(p);
        r.fp.f1 = *reinterpret_cast<const float4*>(p + 4);
    } else {
        r.bf.vh = *reinterpret_cast<const uint4*>(&gh[(size_t)(grow0 + lr) * ld + kt + lk]);
        r.bf.vl = *reinterpret_cast<const uint4*>(&gl[(size_t)(grow0 + lr) * ld + kt + lk]);
    }
}

__device__ __forceinline__ void store_regs(
    __nv_bfloat16* sh, __nv_bfloat16* sl, const LoadRegs& r,
    bool isFp, int lr, int lk) {
    if (isFp) {
        __nv_bfloat16 h0,l0,h1,l1,h2,l2,h3,l3,h4,l4,h5,l5,h6,l6,h7,l7;
        split_bf16(r.fp.f0.x, h0, l0); split_bf16(r.fp.f0.y, h1, l1);
        split_bf16(r.fp.f0.z, h2, l2); split_bf16(r.fp.f0.w, h3, l3);
        split_bf16(r.fp.f1.x, h4, l4); split_bf16(r.fp.f1.y, h5, l5);
        split_bf16(r.fp.f1.z, h6, l6); split_bf16(r.fp.f1.w, h7, l7);
        uint4 vh = make_uint4(pack2(h0,h1), pack2(h2,h3), pack2(h4,h5), pack2(h6,h7));
        uint4 vl = make_uint4(pack2(l0,l1), pack2(l2,l3), pack2(l4,l5), pack2(l6,l7));
        *reinterpret_cast<uint4*>(&sh[lr * SPAD + lk]) = vh;
        *reinterpret_cast<uint4*>(&sl[lr * SPAD + lk]) = vl;
    } else {
        *reinterpret_cast<uint4*>(&sh[lr * SPAD + lk]) = r.bf.vh;
        *reinterpret_cast<uint4*>(&sl[lr * SPAD + lk]) = r.bf.vl;
    }
}

__global__ __launch_bounds__(256) void tgemm_kernel(
    const __nv_bfloat16* __restrict__ Ah0, const __nv_bfloat16* __restrict__ Al0,
    const float* __restrict__ Af0,
    const __nv_bfloat16* __restrict__ Ah1, const __nv_bfloat16* __restrict__ Al1,
    const float* __restrict__ Af1,
    const float* __restrict__ Wf0, const float* __restrict__ Wf1,
    const float* __restrict__ b0, const float* __restrict__ b1,
    float* __restrict__ Cf, __nv_bfloat16* __restrict__ Chi, __nv_bfloat16* __restrict__ Clo,
    int halfM, int Nn, int Kk, int doRelu) {

    __shared__ __align__(16) __nv_bfloat16 sAh[64 * SPAD];
    __shared__ __align__(16) __nv_bfloat16 sAl[64 * SPAD];
    __shared__ __align__(16) __nv_bfloat16 sWh[64 * SPAD];
    __shared__ __align__(16) __nv_bfloat16 sWl[64 * SPAD];

    const int tid  = threadIdx.x;
    const int wid  = tid >> 5;
    const int lane = tid & 31;
    const int gid  = lane >> 2;   // 0..7
    const int tig  = lane & 3;    // 0..3

    const int row0 = blockIdx.y * 64;
    const int col0 = blockIdx.x * 64;
    const bool hi2 = (row0 >= halfM);
    const __nv_bfloat16* __restrict__ Ah = hi2 ? Ah1 : Ah0;
    const __nv_bfloat16* __restrict__ Al = hi2 ? Al1 : Al0;
    const float* __restrict__ Af = hi2 ? Af1 : Af0;
    const float* __restrict__ Wf = hi2 ? Wf1 : Wf0;
    const float* __restrict__ bias = hi2 ? b1 : b0;
    const int arow0 = row0 - (hi2 ? halfM : 0);
    const bool aFp = (Af != nullptr);

    const int warp_m = wid >> 2;  // 0..1
    const int warp_n = wid & 3;   // 0..3

    float acc[2][2][4];
#pragma unroll
    for (int mi = 0; mi < 2; mi++)
#pragma unroll
        for (int ni = 0; ni < 2; ni++)
#pragma unroll
            for (int j = 0; j < 4; j++) acc[mi][ni][j] = 0.0f;

    const int lr = tid >> 2;          // load row 0..63
    const int lk = (tid & 3) * 8;     // load k offset 0,8,16,24

    const int NC = Kk >> 5;
    LoadRegs ra, rw;
    load_regs(ra, Ah, Al, Af, arow0, Kk, 0, lr, lk);
    load_regs(rw, nullptr, nullptr, Wf, col0, Kk, 0, lr, lk);

    for (int c = 0; c < NC; c++) {
        store_regs(sAh, sAl, ra, aFp, lr, lk);
        store_regs(sWh, sWl, rw, true, lr, lk);
        __syncthreads();

        if (c + 1 < NC) {
            const int kt = (c + 1) * 32;
            load_regs(ra, Ah, Al, Af, arow0, Kk, kt, lr, lk);
            load_regs(rw, nullptr, nullptr, Wf, col0, Kk, kt, lr, lk);
        }

#pragma unroll
        for (int ks = 0; ks < 2; ks++) {
            const int kk = ks * 16 + tig * 2;
            uint32_t ah[2][4], al[2][4];
#pragma unroll
            for (int mi = 0; mi < 2; mi++) {
                const int rb = warp_m * 32 + mi * 16;
                ah[mi][0] = *reinterpret_cast<const uint32_t*>(&sAh[(rb + gid) * SPAD + kk]);
                ah[mi][1] = *reinterpret_cast<const uint32_t*>(&sAh[(rb + gid + 8) * SPAD + kk]);
                ah[mi][2] = *reinterpret_cast<const uint32_t*>(&sAh[(rb + gid) * SPAD + kk + 8]);
                ah[mi][3] = *reinterpret_cast<const uint32_t*>(&sAh[(rb + gid + 8) * SPAD + kk + 8]);
                al[mi][0] = *reinterpret_cast<const uint32_t*>(&sAl[(rb + gid) * SPAD + kk]);
                al[mi][1] = *reinterpret_cast<const uint32_t*>(&sAl[(rb + gid + 8) * SPAD + kk]);
                al[mi][2] = *reinterpret_cast<const uint32_t*>(&sAl[(rb + gid) * SPAD + kk + 8]);
                al[mi][3] = *reinterpret_cast<const uint32_t*>(&sAl[(rb + gid + 8) * SPAD + kk + 8]);
            }
            uint32_t bh[2][2], bl[2][2];
#pragma unroll
            for (int ni = 0; ni < 2; ni++) {
                const int nr = warp_n * 16 + ni * 8 + gid;
                bh[ni][0] = *reinterpret_cast<const uint32_t*>(&sWh[nr * SPAD + kk]);
                bh[ni][1] = *reinterpret_cast<const uint32_t*>(&sWh[nr * SPAD + kk + 8]);
                bl[ni][0] = *reinterpret_cast<const uint32_t*>(&sWl[nr * SPAD + kk]);
                bl[ni][1] = *reinterpret_cast<const uint32_t*>(&sWl[nr * SPAD + kk + 8]);
            }
#pragma unroll
            for (int mi = 0; mi < 2; mi++)
#pragma unroll
                for (int ni = 0; ni < 2; ni++) {
                    mma_bf16(acc[mi][ni], ah[mi], bh[ni]);
                    mma_bf16(acc[mi][ni], ah[mi], bl[ni]);
                    mma_bf16(acc[mi][ni], al[mi], bh[ni]);
                }
        }
        __syncthreads();
    }

    // ---- epilogue: bias + activation + stores ----
#pragma unroll
    for (int mi = 0; mi < 2; mi++) {
#pragma unroll
        for (int ni = 0; ni < 2; ni++) {
            const int r0 = row0 + warp_m * 32 + mi * 16 + gid;
            const int c  = col0 + warp_n * 16 + ni * 8 + tig * 2;
            const float bx = bias[c];
            const float by = bias[c + 1];
            float v0 = acc[mi][ni][0] + bx;
            float v1 = acc[mi][ni][1] + by;
            float v2 = acc[mi][ni][2] + bx;
            float v3 = acc[mi][ni][3] + by;
            if (doRelu) {
                v0 = fmaxf(v0, 0.0f); v1 = fmaxf(v1, 0.0f);
                v2 = fmaxf(v2, 0.0f); v3 = fmaxf(v3, 0.0f);
            }
            if (Cf) {
                *reinterpret_cast<float2*>(&Cf[(size_t)r0 * Nn + c])       = make_float2(v0, v1);
                *reinterpret_cast<float2*>(&Cf[(size_t)(r0 + 8) * Nn + c]) = make_float2(v2, v3);
            }
            if (Chi) {
                __nv_bfloat16 h0, l0, h1, l1;
                split_bf16(v0, h0, l0); split_bf16(v1, h1, l1);
                *reinterpret_cast<uint32_t*>(&Chi[(size_t)r0 * Nn + c]) = pack2(h0, h1);
                *reinterpret_cast<uint32_t*>(&Clo[(size_t)r0 * Nn + c]) = pack2(l0, l1);
                split_bf16(v2, h0, l0); split_bf16(v3, h1, l1);
                *reinterpret_cast<uint32_t*>(&Chi[(size_t)(r0 + 8) * Nn + c]) = pack2(h0, h1);
                *reinterpret_cast<uint32_t*>(&Clo[(size_t)(r0 + 8) * Nn + c]) = pack2(l0, l1);
            }
        }
    }
}

// ---------------- deterministic segment mean (4 nodes per block) ----------------
// Stage all 2048 edge ids once per block, then match 4 nodes against each
// staged value (register reuse). Per-node ordered edge lists preserve the
// exact ascending-edge summation order.
#define NPB 4
__global__ __launch_bounds__(256) void segment_kernel(const int* __restrict__ src,
                                                      const int* __restrict__ tgt) {
    __shared__ int s_ids[2 * BB];
    __shared__ int s_list[NPB][2 * BB];
    __shared__ int s_wbase[NPB][8];
    __shared__ int s_total[NPB];
    const int n0  = blockIdx.x * NPB;
    const int tid = threadIdx.x;
    const int wid = tid >> 5;
    const int lid = tid & 31;

#pragma unroll
    for (int i = 0; i < 8; i++) {
        int e = tid + i * 256;
        s_ids[e] = (e < BB) ? src[e] : tgt[e - BB];
    }
    __syncthreads();

    const int chunk0 = wid * 256;

    // pass 1: per-warp match counts for all 4 nodes
    int cnt[NPB] = {0, 0, 0, 0};
#pragma unroll
    for (int r = 0; r < 8; r++) {
        int v = s_ids[chunk0 + r * 32 + lid];
#pragma unroll
        for (int j = 0; j < NPB; j++) {
            unsigned m = __ballot_sync(0xffffffffu, v == n0 + j);
            cnt[j] += __popc(m);
        }
    }
    if (lid == 0) {
#pragma unroll
        for (int j = 0; j < NPB; j++) s_wbase[j][wid] = cnt[j];
    }
    __syncthreads();

    if (tid < NPB) {
        int acc = 0;
#pragma unroll
        for (int w = 0; w < 8; w++) { int c = s_wbase[tid][w]; s_wbase[tid][w] = acc; acc += c; }
        s_total[tid] = acc;
    }
    __syncthreads();

    // pass 2: write ordered edge lists
    int base[NPB];
#pragma unroll
    for (int j = 0; j < NPB; j++) base[j] = s_wbase[j][wid];
#pragma unroll
    for (int r = 0; r < 8; r++) {
        int e = chunk0 + r * 32 + lid;
        int v = s_ids[e];
#pragma unroll
        for (int j = 0; j < NPB; j++) {
            bool hit = (v == n0 + j);
            unsigned m = __ballot_sync(0xffffffffu, hit);
            if (hit) s_list[j][base[j] + __popc(m & ((1u << lid) - 1u))] = e;
            base[j] += __popc(m);
        }
    }
    __syncthreads();

    // reductions (ascending edge order per node)
#pragma unroll 1
    for (int j = 0; j < NPB; j++) {
        const int n = n0 + j;
        const int total = s_total[j];
        float sum = 0.0f;
        for (int i = 0; i < total; i++) {
            int e = s_list[j][i];
            sum += g_MSG[(size_t)e * DD + tid];
        }
        float denom = (total > 0) ? (float)total : 1.0f;
        float mean = sum / denom;
        __nv_bfloat16 h, l;
        split_bf16(mean, h, l);
        g_AGGh[(size_t)n * DD + tid] = h;
        g_AGGl[(size_t)n * DD + tid] = l;
        if (tid == 0) g_CNT[n] = total;
    }
}

// ---------------- GRU gates + masked write ----------------
__global__ void gate_kernel(const float* __restrict__ memory,
                            float* __restrict__ out) {
    const int n = blockIdx.x;
    const int d = threadIdx.x;
    const float* gi = g_G + (size_t)n * K3;
    const float* gh = g_G + (size_t)(NN + n) * K3;

    float r  = 1.0f / (1.0f + expf(-(gi[d] + gh[d])));
    float z  = 1.0f / (1.0f + expf(-(gi[DD + d] + gh[DD + d])));
    float nn = tanhf(gi[2 * DD + d] + r * gh[2 * DD + d]);
    float h  = memory[(size_t)n * DD + d];
    float nv = (1.0f - z) * nn + z * h;
    out[(size_t)n * DD + d] = (g_CNT[n] > 0) ? nv : h;
}

// ---------------- launch ----------------
extern "C" void kernel_launch(void* const* d_in, const int* in_sizes, int n_in,
                              void* d_out, int out_size) {
    const float* memory  = (const float*)d_in[0];
    const int*   source  = (const int*)d_in[1];
    const int*   target  = (const int*)d_in[2];
    const float* dtv     = (const float*)d_in[3];
    const float* src_w1  = (const float*)d_in[4];
    const float* src_b1  = (const float*)d_in[5];
    const float* src_w2  = (const float*)d_in[6];
    const float* src_b2  = (const float*)d_in[7];
    const float* tar_w1  = (const float*)d_in[8];
    const float* tar_b1  = (const float*)d_in[9];
    const float* tar_w2  = (const float*)d_in[10];
    const float* tar_b2  = (const float*)d_in[11];
    const float* gru_wih = (const float*)d_in[12];
    const float* gru_whh = (const float*)d_in[13];
    const float* gru_bih = (const float*)d_in[14];
    const float* gru_bhh = (const float*)d_in[15];
    float* out = (float*)d_out;

    __nv_bfloat16 *pXh, *pXl, *pHh, *pHl, *pAGGh, *pAGGl;
    float *pMSG, *pG;
    cudaGetSymbolAddress((void**)&pXh, g_Xh);   cudaGetSymbolAddress((void**)&pXl, g_Xl);
    cudaGetSymbolAddress((void**)&pHh, g_Hh);   cudaGetSymbolAddress((void**)&pHl, g_Hl);
    cudaGetSymbolAddress((void**)&pAGGh, g_AGGh); cudaGetSymbolAddress((void**)&pAGGl, g_AGGl);
    cudaGetSymbolAddress((void**)&pMSG, g_MSG); cudaGetSymbolAddress((void**)&pG, g_G);

    // 1) gather concat inputs (bf16 hi/lo)
    gather_kernel<<<BB, DD>>>(memory, source, target, dtv);

    // 2) MLP layer 1 (relu): X[2048,768] -> H[2048,256] (bf16 hi/lo out)
    tgemm_kernel<<<dim3(DD / 64, (2 * BB) / 64), 256>>>(
        pXh, pXl, nullptr,
        pXh + (size_t)BB * K3, pXl + (size_t)BB * K3, nullptr,
        src_w1, tar_w1,
        src_b1, tar_b1, nullptr, pHh, pHl, BB, DD, K3, 1);

    // 3) MLP layer 2: H[2048,256] -> MSG[2048,256] fp32
    tgemm_kernel<<<dim3(DD / 64, (2 * BB) / 64), 256>>>(
        pHh, pHl, nullptr,
        pHh + (size_t)BB * DD, pHl + (size_t)BB * DD, nullptr,
        src_w2, tar_w2,
        src_b2, tar_b2, pMSG, nullptr, nullptr, BB, DD, DD, 0);

    // 4) deterministic segment mean -> AGG hi/lo, CNT (4 nodes/block)
    segment_kernel<<<NN / NPB, 256>>>(source, target);

    // 5) GRU preactivations: gi = agg@wih^T + bih ; gh = memory@whh^T + bhh
    tgemm_kernel<<<dim3(K3 / 64, (2 * NN) / 64), 256>>>(
        pAGGh, pAGGl, nullptr,
        nullptr, nullptr, memory,
        gru_wih, gru_whh,
        gru_bih, gru_bhh, pG, nullptr, nullptr, NN, K3, DD, 0);

    // 6) gates + masked output
    gate_kernel<<<NN, DD>>>(memory, out);
}